// round 13
// baseline (speedup 1.0000x reference)
#include <cuda_runtime.h>
#include <cuda.h>
#include <cstddef>
#include <cstdint>

namespace {

constexpr int B = 2, N = 512, C = 64, H = 8;
constexpr int THREADS = 256;            // 2 n-rows per thread
constexpr int SCH    = 16;              // channels per stage
constexpr int STAGES = 8;               // 4 q-stages + 4 k-stages
constexpr int NBUF   = 2;               // ring depth (fit 3 CTAs/SM)
constexpr int BUF_F4 = 512 * 4;         // 2048 float4 = 32 KB per buffer (TMA SW64 layout)
constexpr int STAGE_BYTES = 512 * 64;   // 32768 bytes per stage

// smem layout (floats):
//   [0..8)      mbar full[2]
//   [8..72)     wsum[8][8]
//   [128..1152) Ws (transposed W, [c][h])
//   [1280..)    ring: NBUF x 8192 floats
constexpr int OFF_MBAR = 0;
constexpr int OFF_WSUM = 8;
constexpr int OFF_WS   = 128;
constexpr int OFF_RING = 1280;
constexpr size_t SMEM_BYTES = (OFF_RING + NBUF * BUF_F4 * 4) * sizeof(float);

#define FMA2(acc, a, b) \
    asm("fma.rn.f32x2 %0, %1, %2, %0;" : "+l"(acc) : "l"(a), "l"(b))

__device__ __forceinline__ unsigned long long pack2(float lo, float hi) {
    unsigned long long d;
    asm("mov.b64 %0, {%1, %2};" : "=l"(d) : "r"(__float_as_uint(lo)), "r"(__float_as_uint(hi)));
    return d;
}
__device__ __forceinline__ void unpack2(unsigned long long v, float& lo, float& hi) {
    unsigned int l, h;
    asm("mov.b64 {%0, %1}, %2;" : "=r"(l), "=r"(h) : "l"(v));
    lo = __uint_as_float(l);
    hi = __uint_as_float(h);
}
__device__ __forceinline__ uint32_t smem_u32(const void* p) {
    return (uint32_t)__cvta_generic_to_shared(p);
}

__device__ __forceinline__ void mbar_init(uint32_t mbar, uint32_t count) {
    asm volatile("mbarrier.init.shared.b64 [%0], %1;" :: "r"(mbar), "r"(count) : "memory");
}
__device__ __forceinline__ void mbar_expect_tx(uint32_t mbar, uint32_t bytes) {
    asm volatile("mbarrier.arrive.expect_tx.shared.b64 _, [%0], %1;" :: "r"(mbar), "r"(bytes) : "memory");
}
__device__ __forceinline__ void mbar_wait(uint32_t mbar, uint32_t parity) {
    uint32_t done;
    asm volatile(
        "{\n\t.reg .pred p;\n\t"
        "mbarrier.try_wait.parity.acquire.cta.shared::cta.b64 p, [%1], %2;\n\t"
        "selp.b32 %0, 1, 0, p;\n\t}"
        : "=r"(done) : "r"(mbar), "r"(parity) : "memory");
    while (!done) {
        asm volatile(
            "{\n\t.reg .pred p;\n\t"
            "mbarrier.try_wait.parity.acquire.cta.shared::cta.b64 p, [%1], %2, 0x989680;\n\t"
            "selp.b32 %0, 1, 0, p;\n\t}"
            : "=r"(done) : "r"(mbar), "r"(parity) : "memory");
    }
}
__device__ __forceinline__ void tma_load_2d(uint32_t smem_addr, const CUtensorMap* tmap,
                                            int32_t x, int32_t y, uint32_t mbar) {
    asm volatile(
        "cp.async.bulk.tensor.2d.shared::cta.global.tile.mbarrier::complete_tx::bytes "
        "[%0], [%1, {%2, %3}], [%4];"
        :: "r"(smem_addr), "l"(tmap), "r"(x), "r"(y), "r"(mbar) : "memory");
}

__global__ __launch_bounds__(THREADS, 3)
void mha_fused_kernel(const __grid_constant__ CUtensorMap qmap,
                      const __grid_constant__ CUtensorMap kmap,
                      const float* __restrict__ roi,
                      const float* __restrict__ W,
                      const float* __restrict__ bias,
                      float* __restrict__ out)
{
    extern __shared__ float smem[];
    float* Ws   = smem + OFF_WS;
    float* wsum = smem + OFF_WSUM;
    float4* ring = reinterpret_cast<float4*>(smem + OFF_RING);
    const uint32_t mbar0 = smem_u32(smem + OFF_MBAR);   // full[i] at mbar0 + 8*i

    const int tid  = threadIdx.x;
    const int bm   = blockIdx.x;                        // b*N + m
    const int warp = tid >> 5;
    const int lane = tid & 31;

    // W[h][128] -> Ws[c][h]
    for (int i = tid; i < 128 * H; i += THREADS) {
        const int h = i >> 7, c = i & 127;
        Ws[c * H + h] = W[i];
    }

    if (tid == 0) {
#pragma unroll
        for (int i = 0; i < NBUF; ++i) mbar_init(mbar0 + 8 * i, 1);
    }
    __syncthreads();   // mbar init + Ws visible

    // stage s: q stages 0..3 at channel s*16; k stages 4..7 at channel (s-4)*16
    auto issue_stage = [&](int s) {
        const int buf = s & 1;
        const uint32_t mb = mbar0 + 8 * buf;
        const uint32_t dst = smem_u32(&ring[buf * BUF_F4]);
        const CUtensorMap* tmap = (s < 4) ? &qmap : &kmap;
        const int x = (s < 4 ? s : s - 4) * SCH;
        const int y = bm * 512;
        mbar_expect_tx(mb, STAGE_BYTES);
        tma_load_2d(dst, tmap, x, y, mb);
        tma_load_2d(dst + STAGE_BYTES / 2, tmap, x, y + 256, mb);
    };

    if (tid == 0) issue_stage(0);

    unsigned long long acc0[4], acc1[4];
    acc0[0] = pack2(bias[0], bias[1]);
    acc0[1] = pack2(bias[2], bias[3]);
    acc0[2] = pack2(bias[4], bias[5]);
    acc0[3] = pack2(bias[6], bias[7]);
#pragma unroll
    for (int j = 0; j < 4; ++j) acc1[j] = acc0[j];

    const int sw = (tid >> 1) & 3;   // SW64 read swizzle (same for tid and tid+256)

#pragma unroll
    for (int s = 0; s < STAGES; ++s) {
        // wait for stage s data; parity = (use count of this buffer) & 1
        mbar_wait(mbar0 + 8 * (s & 1), (s >> 1) & 1);
        __syncthreads();   // all threads done reading buf (s+1)&1 (stage s-1's data)
        if (tid == 0 && s + 1 < STAGES) issue_stage(s + 1);  // overlaps compute below

        const float4* base = ring + (s & 1) * BUF_F4;
        const ulonglong2* wp = reinterpret_cast<const ulonglong2*>(
            &Ws[((s < 4 ? s * SCH : 64 + (s - 4) * SCH)) * H]);

#pragma unroll
        for (int j = 0; j < 4; ++j) {
            // just-in-time loads: only 2 live float4 (register budget for occ=3)
            const float4 v0 = base[tid * 4 + (j ^ sw)];
            const float4 v1 = base[1024 + tid * 4 + (j ^ sw)];
            const float a0v[4] = {v0.x, v0.y, v0.z, v0.w};
            const float a1v[4] = {v1.x, v1.y, v1.z, v1.w};
#pragma unroll
            for (int cc = 0; cc < 4; ++cc) {
                const int c = j * 4 + cc;
                const ulonglong2 w01 = wp[c * 2];         // heads 0-3
                const ulonglong2 w45 = wp[c * 2 + 1];     // heads 4-7
                const unsigned long long a0 = pack2(a0v[cc], a0v[cc]);
                const unsigned long long a1 = pack2(a1v[cc], a1v[cc]);
                FMA2(acc0[0], a0, w01.x);
                FMA2(acc0[1], a0, w01.y);
                FMA2(acc0[2], a0, w45.x);
                FMA2(acc0[3], a0, w45.y);
                FMA2(acc1[0], a1, w01.x);
                FMA2(acc1[1], a1, w01.y);
                FMA2(acc1[2], a1, w45.x);
                FMA2(acc1[3], a1, w45.y);
            }
        }
    }

    // ---- epilogue: exp * roi for both rows ----
    float e0[H], e1[H], sums[H];
    {
        float a0[H], a1[H];
#pragma unroll
        for (int j = 0; j < 4; ++j) {
            unpack2(acc0[j], a0[2 * j], a0[2 * j + 1]);
            unpack2(acc1[j], a1[2 * j], a1[2 * j + 1]);
        }
        const float r0v = roi[(size_t)bm * N + tid];
        const float r1v = roi[(size_t)bm * N + tid + 256];
#pragma unroll
        for (int h = 0; h < H; ++h) {
            e0[h] = __expf(a0[h]) * r0v;
            e1[h] = __expf(a1[h]) * r1v;
            sums[h] = e0[h] + e1[h];
        }
    }

    // ---- block-wide row-sum over all 512 n ----
#pragma unroll
    for (int h = 0; h < H; ++h) {
        float s = sums[h];
#pragma unroll
        for (int off = 16; off > 0; off >>= 1)
            s += __shfl_xor_sync(0xffffffffu, s, off);
        sums[h] = s;
    }
    if (lane == 0) {
#pragma unroll
        for (int h = 0; h < H; ++h) wsum[warp * H + h] = sums[h];
    }
    __syncthreads();

    float inv[H];
#pragma unroll
    for (int h = 0; h < H; ++h) {
        float t = 0.f;
#pragma unroll
        for (int w = 0; w < 8; ++w) t += wsum[w * H + h];
        inv[h] = 1.0f / t;
    }

    // ---- normalize + store (2x STG.128 per row) ----
    {
        float* op = out + ((size_t)bm * N + tid) * H;
        float4 a, b2;
        a.x  = e0[0] * inv[0];  a.y  = e0[1] * inv[1];
        a.z  = e0[2] * inv[2];  a.w  = e0[3] * inv[3];
        b2.x = e0[4] * inv[4];  b2.y = e0[5] * inv[5];
        b2.z = e0[6] * inv[6];  b2.w = e0[7] * inv[7];
        *reinterpret_cast<float4*>(op)     = a;
        *reinterpret_cast<float4*>(op + 4) = b2;
    }
    {
        float* op = out + ((size_t)bm * N + tid + 256) * H;
        float4 a, b2;
        a.x  = e1[0] * inv[0];  a.y  = e1[1] * inv[1];
        a.z  = e1[2] * inv[2];  a.w  = e1[3] * inv[3];
        b2.x = e1[4] * inv[4];  b2.y = e1[5] * inv[5];
        b2.z = e1[6] * inv[6];  b2.w = e1[7] * inv[7];
        *reinterpret_cast<float4*>(op)     = a;
        *reinterpret_cast<float4*>(op + 4) = b2;
    }
}

// runtime-resolved driver API (harness doesn't link -lcuda)
typedef CUresult (*EncodeTiledFn)(
    CUtensorMap*, CUtensorMapDataType, cuuint32_t, void*,
    const cuuint64_t*, const cuuint64_t*, const cuuint32_t*, const cuuint32_t*,
    CUtensorMapInterleave, CUtensorMapSwizzle, CUtensorMapL2promotion,
    CUtensorMapFloatOOBfill);

static EncodeTiledFn get_encode_fn() {
    void* fn = nullptr;
    cudaDriverEntryPointQueryResult qr;
    cudaGetDriverEntryPoint("cuTensorMapEncodeTiled", &fn, cudaEnableDefault, &qr);
    return (EncodeTiledFn)fn;
}

static CUtensorMap make_map(EncodeTiledFn enc, const void* ptr) {
    CUtensorMap m{};
    cuuint64_t dims[2]    = {(cuuint64_t)C, (cuuint64_t)B * N * N};  // 64 floats wide, 524288 rows
    cuuint64_t strides[1] = {(cuuint64_t)(C * sizeof(float))};       // 256 B row stride
    cuuint32_t box[2]     = {SCH, 256};                              // 64 B x 256 rows per load
    cuuint32_t estr[2]    = {1, 1};
    enc(&m, CU_TENSOR_MAP_DATA_TYPE_FLOAT32, 2,
        const_cast<void*>(ptr), dims, strides, box, estr,
        CU_TENSOR_MAP_INTERLEAVE_NONE,
        CU_TENSOR_MAP_SWIZZLE_64B,
        CU_TENSOR_MAP_L2_PROMOTION_L2_128B,
        CU_TENSOR_MAP_FLOAT_OOB_FILL_NONE);
    return m;
}

} // namespace

extern "C" void kernel_launch(void* const* d_in, const int* in_sizes, int n_in,
                              void* d_out, int out_size)
{
    const float* q    = (const float*)d_in[0];
    const float* k    = (const float*)d_in[1];
    const float* roi  = (const float*)d_in[2];
    const float* W    = (const float*)d_in[3];
    const float* bias = (const float*)d_in[4];
    float* out        = (float*)d_out;

    (void)in_sizes; (void)n_in; (void)out_size;

    EncodeTiledFn enc = get_encode_fn();
    const CUtensorMap qmap = make_map(enc, q);
    const CUtensorMap kmap = make_map(enc, k);

    cudaFuncSetAttribute(mha_fused_kernel,
                         cudaFuncAttributeMaxDynamicSharedMemorySize,
                         (int)SMEM_BYTES);

    dim3 grid(B * N);     // one block per (b, m) row
    dim3 block(THREADS);
    mha_fused_kernel<<<grid, block, SMEM_BYTES>>>(qmap, kmap, roi, W, bias, out);
}

// round 16
// speedup vs baseline: 1.1499x; 1.1499x over previous
#include <cuda_runtime.h>
#include <cuda.h>
#include <cstddef>
#include <cstdint>

namespace {

constexpr int B = 2, N = 512, C = 64, H = 8;
constexpr int THREADS = 256;            // 2 n-rows per thread
constexpr int SCH    = 16;              // channels per stage
constexpr int ROWS_PER_CTA = 4;         // grid 256, rows c, c+256, c+512, c+768
constexpr int GRID   = 256;
constexpr int STAGES_PER_ROW = 8;       // 4 q + 4 k
constexpr int TOT_STAGES = ROWS_PER_CTA * STAGES_PER_ROW;   // 32
constexpr int NBUF   = 3;               // ring depth
constexpr int BUF_F4 = 512 * 4;         // 2048 float4 = 32 KB per buffer (TMA SW64 layout)
constexpr int STAGE_BYTES = 512 * 64;   // 32768 bytes per stage

constexpr int OFF_MBAR = 0;
constexpr int OFF_WSUM = 8;
constexpr int OFF_WS   = 128;
constexpr int OFF_RING = 1280;
constexpr size_t SMEM_BYTES = (OFF_RING + NBUF * BUF_F4 * 4) * sizeof(float);

#define FMA2(acc, a, b) \
    asm("fma.rn.f32x2 %0, %1, %2, %0;" : "+l"(acc) : "l"(a), "l"(b))

__device__ __forceinline__ unsigned long long pack2(float lo, float hi) {
    unsigned long long d;
    asm("mov.b64 %0, {%1, %2};" : "=l"(d) : "r"(__float_as_uint(lo)), "r"(__float_as_uint(hi)));
    return d;
}
__device__ __forceinline__ void unpack2(unsigned long long v, float& lo, float& hi) {
    unsigned int l, h;
    asm("mov.b64 {%0, %1}, %2;" : "=r"(l), "=r"(h) : "l"(v));
    lo = __uint_as_float(l);
    hi = __uint_as_float(h);
}
__device__ __forceinline__ uint32_t smem_u32(const void* p) {
    return (uint32_t)__cvta_generic_to_shared(p);
}

__device__ __forceinline__ void mbar_init(uint32_t mbar, uint32_t count) {
    asm volatile("mbarrier.init.shared.b64 [%0], %1;" :: "r"(mbar), "r"(count) : "memory");
}
__device__ __forceinline__ void mbar_expect_tx(uint32_t mbar, uint32_t bytes) {
    asm volatile("mbarrier.arrive.expect_tx.shared.b64 _, [%0], %1;" :: "r"(mbar), "r"(bytes) : "memory");
}
__device__ __forceinline__ void mbar_wait(uint32_t mbar, uint32_t parity) {
    uint32_t done;
    asm volatile(
        "{\n\t.reg .pred p;\n\t"
        "mbarrier.try_wait.parity.acquire.cta.shared::cta.b64 p, [%1], %2;\n\t"
        "selp.b32 %0, 1, 0, p;\n\t}"
        : "=r"(done) : "r"(mbar), "r"(parity) : "memory");
    while (!done) {
        asm volatile(
            "{\n\t.reg .pred p;\n\t"
            "mbarrier.try_wait.parity.acquire.cta.shared::cta.b64 p, [%1], %2, 0x989680;\n\t"
            "selp.b32 %0, 1, 0, p;\n\t}"
            : "=r"(done) : "r"(mbar), "r"(parity) : "memory");
    }
}
__device__ __forceinline__ void tma_load_2d(uint32_t smem_addr, const CUtensorMap* tmap,
                                            int32_t x, int32_t y, uint32_t mbar) {
    asm volatile(
        "cp.async.bulk.tensor.2d.shared::cta.global.tile.mbarrier::complete_tx::bytes "
        "[%0], [%1, {%2, %3}], [%4];"
        :: "r"(smem_addr), "l"(tmap), "r"(x), "r"(y), "r"(mbar) : "memory");
}

__global__ __launch_bounds__(THREADS, 2)
void mha_fused_kernel(const __grid_constant__ CUtensorMap qmap,
                      const __grid_constant__ CUtensorMap kmap,
                      const float* __restrict__ roi,
                      const float* __restrict__ W,
                      const float* __restrict__ bias,
                      float* __restrict__ out)
{
    extern __shared__ float smem[];
    float* Ws   = smem + OFF_WS;
    float* wsum = smem + OFF_WSUM;
    float4* ring = reinterpret_cast<float4*>(smem + OFF_RING);
    const uint32_t mbar0 = smem_u32(smem + OFF_MBAR);

    const int tid  = threadIdx.x;
    const int bid  = blockIdx.x;        // handles rows bid + r*256, r=0..3
    const int warp = tid >> 5;
    const int lane = tid & 31;

    // W[h][128] -> Ws[c][h]
    for (int i = tid; i < 128 * H; i += THREADS) {
        const int h = i >> 7, c = i & 127;
        Ws[c * H + h] = W[i];
    }

    if (tid == 0) {
#pragma unroll
        for (int i = 0; i < NBUF; ++i) mbar_init(mbar0 + 8 * i, 1);
    }
    __syncthreads();

    // global stage g = r*8 + s:  row bm = bid + (g>>3)*256;  s = g&7
    auto issue_stage = [&](int g, int buf) {
        const uint32_t mb = mbar0 + 8 * buf;
        const uint32_t dst = smem_u32(&ring[buf * BUF_F4]);
        const int s = g & 7;
        const CUtensorMap* tmap = (s < 4) ? &qmap : &kmap;
        const int x = (s & 3) * SCH;
        const int y = (bid + (g >> 3) * GRID) * 512;
        mbar_expect_tx(mb, STAGE_BYTES);
        tma_load_2d(dst, tmap, x, y, mb);
        tma_load_2d(dst + STAGE_BYTES / 2, tmap, x, y + 256, mb);
    };

    if (tid == 0) { issue_stage(0, 0); issue_stage(1, 1); }

    const unsigned long long b01 = pack2(bias[0], bias[1]);
    const unsigned long long b23 = pack2(bias[2], bias[3]);
    const unsigned long long b45 = pack2(bias[4], bias[5]);
    const unsigned long long b67 = pack2(bias[6], bias[7]);

    const int sw = (tid >> 1) & 3;      // SW64 read swizzle

    int cbuf = 0, cph = 0;              // consumer cursor
    int pbuf = 2;                       // producer cursor (next issue = stage g+2)

    for (int r = 0; r < ROWS_PER_CTA; ++r) {
        const int bm = bid + r * GRID;

        unsigned long long acc0[4], acc1[4];
        acc0[0] = b01; acc0[1] = b23; acc0[2] = b45; acc0[3] = b67;
#pragma unroll
        for (int j = 0; j < 4; ++j) acc1[j] = acc0[j];

#pragma unroll
        for (int s = 0; s < STAGES_PER_ROW; ++s) {
            mbar_wait(mbar0 + 8 * cbuf, cph);
            const float4* base = ring + cbuf * BUF_F4;
            if (++cbuf == NBUF) { cbuf = 0; cph ^= 1; }

            const int gn = r * 8 + s + 2;
            if (tid == 0 && gn < TOT_STAGES) {
                issue_stage(gn, pbuf);
            }
            if (gn < TOT_STAGES) { if (++pbuf == NBUF) pbuf = 0; }

            // read this thread's two half-rows, then free the buffer
            float4 d0[4], d1[4];
#pragma unroll
            for (int j = 0; j < 4; ++j) {
                d0[j] = base[tid * 4 + (j ^ sw)];
                d1[j] = base[1024 + tid * 4 + (j ^ sw)];
            }
            __syncthreads();   // all reads done -> buffer free for issue next iteration

            const ulonglong2* wp = reinterpret_cast<const ulonglong2*>(
                &Ws[((s < 4 ? s * SCH : 64 + (s - 4) * SCH)) * H]);
#pragma unroll
            for (int j = 0; j < 4; ++j) {
                const float a0v[4] = {d0[j].x, d0[j].y, d0[j].z, d0[j].w};
                const float a1v[4] = {d1[j].x, d1[j].y, d1[j].z, d1[j].w};
#pragma unroll
                for (int cc = 0; cc < 4; ++cc) {
                    const int c = j * 4 + cc;
                    const ulonglong2 w01 = wp[c * 2];         // heads 0-3
                    const ulonglong2 w45 = wp[c * 2 + 1];     // heads 4-7
                    const unsigned long long a0 = pack2(a0v[cc], a0v[cc]);
                    const unsigned long long a1 = pack2(a1v[cc], a1v[cc]);
                    FMA2(acc0[0], a0, w01.x);
                    FMA2(acc0[1], a0, w01.y);
                    FMA2(acc0[2], a0, w45.x);
                    FMA2(acc0[3], a0, w45.y);
                    FMA2(acc1[0], a1, w01.x);
                    FMA2(acc1[1], a1, w01.y);
                    FMA2(acc1[2], a1, w45.x);
                    FMA2(acc1[3], a1, w45.y);
                }
            }
        }

        // ---- epilogue for row bm: exp * roi, reduce, normalize, store ----
        float e0[H], e1[H], sums[H];
        {
            float a0[H], a1[H];
#pragma unroll
            for (int j = 0; j < 4; ++j) {
                unpack2(acc0[j], a0[2 * j], a0[2 * j + 1]);
                unpack2(acc1[j], a1[2 * j], a1[2 * j + 1]);
            }
            const float r0v = roi[(size_t)bm * N + tid];
            const float r1v = roi[(size_t)bm * N + tid + 256];
#pragma unroll
            for (int h = 0; h < H; ++h) {
                e0[h] = __expf(a0[h]) * r0v;
                e1[h] = __expf(a1[h]) * r1v;
                sums[h] = e0[h] + e1[h];
            }
        }

#pragma unroll
        for (int h = 0; h < H; ++h) {
            float s = sums[h];
#pragma unroll
            for (int off = 16; off > 0; off >>= 1)
                s += __shfl_xor_sync(0xffffffffu, s, off);
            sums[h] = s;
        }
        if (lane == 0) {
#pragma unroll
            for (int h = 0; h < H; ++h) wsum[warp * H + h] = sums[h];
        }
        __syncthreads();

        float inv[H];
#pragma unroll
        for (int h = 0; h < H; ++h) {
            float t = 0.f;
#pragma unroll
            for (int w = 0; w < 8; ++w) t += wsum[w * H + h];
            inv[h] = 1.0f / t;
        }
        __syncthreads();   // wsum consumed before next row overwrites

        {
            float* op = out + ((size_t)bm * N + tid) * H;
            float4 a, b2;
            a.x  = e0[0] * inv[0];  a.y  = e0[1] * inv[1];
            a.z  = e0[2] * inv[2];  a.w  = e0[3] * inv[3];
            b2.x = e0[4] * inv[4];  b2.y = e0[5] * inv[5];
            b2.z = e0[6] * inv[6];  b2.w = e0[7] * inv[7];
            *reinterpret_cast<float4*>(op)     = a;
            *reinterpret_cast<float4*>(op + 4) = b2;
        }
        {
            float* op = out + ((size_t)bm * N + tid + 256) * H;
            float4 a, b2;
            a.x  = e1[0] * inv[0];  a.y  = e1[1] * inv[1];
            a.z  = e1[2] * inv[2];  a.w  = e1[3] * inv[3];
            b2.x = e1[4] * inv[4];  b2.y = e1[5] * inv[5];
            b2.z = e1[6] * inv[6];  b2.w = e1[7] * inv[7];
            *reinterpret_cast<float4*>(op)     = a;
            *reinterpret_cast<float4*>(op + 4) = b2;
        }
    }
}

// runtime-resolved driver API (harness doesn't link -lcuda)
typedef CUresult (*EncodeTiledFn)(
    CUtensorMap*, CUtensorMapDataType, cuuint32_t, void*,
    const cuuint64_t*, const cuuint64_t*, const cuuint32_t*, const cuuint32_t*,
    CUtensorMapInterleave, CUtensorMapSwizzle, CUtensorMapL2promotion,
    CUtensorMapFloatOOBfill);

static EncodeTiledFn get_encode_fn() {
    void* fn = nullptr;
    cudaDriverEntryPointQueryResult qr;
    cudaGetDriverEntryPoint("cuTensorMapEncodeTiled", &fn, cudaEnableDefault, &qr);
    return (EncodeTiledFn)fn;
}

static CUtensorMap make_map(EncodeTiledFn enc, const void* ptr) {
    CUtensorMap m{};
    cuuint64_t dims[2]    = {(cuuint64_t)C, (cuuint64_t)B * N * N};
    cuuint64_t strides[1] = {(cuuint64_t)(C * sizeof(float))};
    cuuint32_t box[2]     = {SCH, 256};
    cuuint32_t estr[2]    = {1, 1};
    enc(&m, CU_TENSOR_MAP_DATA_TYPE_FLOAT32, 2,
        const_cast<void*>(ptr), dims, strides, box, estr,
        CU_TENSOR_MAP_INTERLEAVE_NONE,
        CU_TENSOR_MAP_SWIZZLE_64B,
        CU_TENSOR_MAP_L2_PROMOTION_L2_128B,
        CU_TENSOR_MAP_FLOAT_OOB_FILL_NONE);
    return m;
}

} // namespace

extern "C" void kernel_launch(void* const* d_in, const int* in_sizes, int n_in,
                              void* d_out, int out_size)
{
    const float* q    = (const float*)d_in[0];
    const float* k    = (const float*)d_in[1];
    const float* roi  = (const float*)d_in[2];
    const float* W    = (const float*)d_in[3];
    const float* bias = (const float*)d_in[4];
    float* out        = (float*)d_out;

    (void)in_sizes; (void)n_in; (void)out_size;

    EncodeTiledFn enc = get_encode_fn();
    const CUtensorMap qmap = make_map(enc, q);
    const CUtensorMap kmap = make_map(enc, k);

    cudaFuncSetAttribute(mha_fused_kernel,
                         cudaFuncAttributeMaxDynamicSharedMemorySize,
                         (int)SMEM_BYTES);

    dim3 grid(GRID);     // 256 CTAs x 4 rows each; single wave
    dim3 block(THREADS);
    mha_fused_kernel<<<grid, block, SMEM_BYTES>>>(qmap, kmap, roi, W, bias, out);
}

// round 17
// speedup vs baseline: 1.1567x; 1.0060x over previous
#include <cuda_runtime.h>
#include <cuda.h>
#include <cstddef>
#include <cstdint>

namespace {

constexpr int B = 2, N = 512, C = 64, H = 8;
constexpr int THREADS = 256;            // 2 n-rows per thread
constexpr int SCH    = 16;              // channels per stage
constexpr int GRID   = 296;             // 148 SMs x 2 CTAs, single wave, balanced
constexpr int TOTROWS = B * N;          // 1024 (b,m) rows
constexpr int STAGES_PER_ROW = 8;       // 4 q + 4 k
constexpr int NBUF   = 3;               // ring depth
constexpr int BUF_F4 = 512 * 4;         // 2048 float4 = 32 KB per buffer (TMA SW64 layout)
constexpr int STAGE_BYTES = 512 * 64;   // 32768 bytes per stage

constexpr int OFF_MBAR = 0;
constexpr int OFF_WSUM = 8;
constexpr int OFF_WS   = 128;
constexpr int OFF_RING = 1280;
constexpr size_t SMEM_BYTES = (OFF_RING + NBUF * BUF_F4 * 4) * sizeof(float);

#define FMA2(acc, a, b) \
    asm("fma.rn.f32x2 %0, %1, %2, %0;" : "+l"(acc) : "l"(a), "l"(b))

__device__ __forceinline__ unsigned long long pack2(float lo, float hi) {
    unsigned long long d;
    asm("mov.b64 %0, {%1, %2};" : "=l"(d) : "r"(__float_as_uint(lo)), "r"(__float_as_uint(hi)));
    return d;
}
__device__ __forceinline__ void unpack2(unsigned long long v, float& lo, float& hi) {
    unsigned int l, h;
    asm("mov.b64 {%0, %1}, %2;" : "=r"(l), "=r"(h) : "l"(v));
    lo = __uint_as_float(l);
    hi = __uint_as_float(h);
}
__device__ __forceinline__ uint32_t smem_u32(const void* p) {
    return (uint32_t)__cvta_generic_to_shared(p);
}

__device__ __forceinline__ void mbar_init(uint32_t mbar, uint32_t count) {
    asm volatile("mbarrier.init.shared.b64 [%0], %1;" :: "r"(mbar), "r"(count) : "memory");
}
__device__ __forceinline__ void mbar_expect_tx(uint32_t mbar, uint32_t bytes) {
    asm volatile("mbarrier.arrive.expect_tx.shared.b64 _, [%0], %1;" :: "r"(mbar), "r"(bytes) : "memory");
}
__device__ __forceinline__ void mbar_wait(uint32_t mbar, uint32_t parity) {
    uint32_t done;
    asm volatile(
        "{\n\t.reg .pred p;\n\t"
        "mbarrier.try_wait.parity.acquire.cta.shared::cta.b64 p, [%1], %2;\n\t"
        "selp.b32 %0, 1, 0, p;\n\t}"
        : "=r"(done) : "r"(mbar), "r"(parity) : "memory");
    while (!done) {
        asm volatile(
            "{\n\t.reg .pred p;\n\t"
            "mbarrier.try_wait.parity.acquire.cta.shared::cta.b64 p, [%1], %2, 0x989680;\n\t"
            "selp.b32 %0, 1, 0, p;\n\t}"
            : "=r"(done) : "r"(mbar), "r"(parity) : "memory");
    }
}
__device__ __forceinline__ void tma_load_2d(uint32_t smem_addr, const CUtensorMap* tmap,
                                            int32_t x, int32_t y, uint32_t mbar) {
    asm volatile(
        "cp.async.bulk.tensor.2d.shared::cta.global.tile.mbarrier::complete_tx::bytes "
        "[%0], [%1, {%2, %3}], [%4];"
        :: "r"(smem_addr), "l"(tmap), "r"(x), "r"(y), "r"(mbar) : "memory");
}

__global__ __launch_bounds__(THREADS, 2)
void mha_fused_kernel(const __grid_constant__ CUtensorMap qmap,
                      const __grid_constant__ CUtensorMap kmap,
                      const float* __restrict__ roi,
                      const float* __restrict__ W,
                      const float* __restrict__ bias,
                      float* __restrict__ out)
{
    extern __shared__ float smem[];
    float* Ws   = smem + OFF_WS;
    float* wsum = smem + OFF_WSUM;
    float4* ring = reinterpret_cast<float4*>(smem + OFF_RING);
    const uint32_t mbar0 = smem_u32(smem + OFF_MBAR);

    const int tid  = threadIdx.x;
    const int bid  = blockIdx.x;        // rows bid + j*296, j = 0..nrows-1
    const int warp = tid >> 5;
    const int lane = tid & 31;

    const int nrows = (TOTROWS - 1 - bid) / GRID + 1;   // 4 for bid<136, else 3
    const int tot_stages = nrows * STAGES_PER_ROW;

    // W[h][128] -> Ws[c][h]
    for (int i = tid; i < 128 * H; i += THREADS) {
        const int h = i >> 7, c = i & 127;
        Ws[c * H + h] = W[i];
    }

    if (tid == 0) {
#pragma unroll
        for (int i = 0; i < NBUF; ++i) mbar_init(mbar0 + 8 * i, 1);
    }
    __syncthreads();

    // global stage g = r*8 + s:  row bm = bid + (g>>3)*GRID;  s = g&7
    auto issue_stage = [&](int g, int buf) {
        const uint32_t mb = mbar0 + 8 * buf;
        const uint32_t dst = smem_u32(&ring[buf * BUF_F4]);
        const int s = g & 7;
        const CUtensorMap* tmap = (s < 4) ? &qmap : &kmap;
        const int x = (s & 3) * SCH;
        const int y = (bid + (g >> 3) * GRID) * 512;
        mbar_expect_tx(mb, STAGE_BYTES);
        tma_load_2d(dst, tmap, x, y, mb);
        tma_load_2d(dst + STAGE_BYTES / 2, tmap, x, y + 256, mb);
    };

    if (tid == 0) { issue_stage(0, 0); issue_stage(1, 1); }

    const unsigned long long b01 = pack2(bias[0], bias[1]);
    const unsigned long long b23 = pack2(bias[2], bias[3]);
    const unsigned long long b45 = pack2(bias[4], bias[5]);
    const unsigned long long b67 = pack2(bias[6], bias[7]);

    const int sw = (tid >> 1) & 3;      // SW64 read swizzle

    int cbuf = 0, cph = 0;              // consumer cursor
    int pbuf = 2;                       // producer cursor (next issue = stage g+2)

    for (int r = 0; r < nrows; ++r) {
        const int bm = bid + r * GRID;

        unsigned long long acc0[4], acc1[4];
        acc0[0] = b01; acc0[1] = b23; acc0[2] = b45; acc0[3] = b67;
#pragma unroll
        for (int j = 0; j < 4; ++j) acc1[j] = acc0[j];

#pragma unroll
        for (int s = 0; s < STAGES_PER_ROW; ++s) {
            mbar_wait(mbar0 + 8 * cbuf, cph);
            const float4* base = ring + cbuf * BUF_F4;
            if (++cbuf == NBUF) { cbuf = 0; cph ^= 1; }

            const int gn = r * 8 + s + 2;
            if (tid == 0 && gn < tot_stages) {
                issue_stage(gn, pbuf);
            }
            if (gn < tot_stages) { if (++pbuf == NBUF) pbuf = 0; }

            // read this thread's two half-rows, then free the buffer
            float4 d0[4], d1[4];
#pragma unroll
            for (int j = 0; j < 4; ++j) {
                d0[j] = base[tid * 4 + (j ^ sw)];
                d1[j] = base[1024 + tid * 4 + (j ^ sw)];
            }
            __syncthreads();   // all reads done -> buffer free for reuse

            const ulonglong2* wp = reinterpret_cast<const ulonglong2*>(
                &Ws[((s < 4 ? s * SCH : 64 + (s - 4) * SCH)) * H]);
#pragma unroll
            for (int j = 0; j < 4; ++j) {
                const float a0v[4] = {d0[j].x, d0[j].y, d0[j].z, d0[j].w};
                const float a1v[4] = {d1[j].x, d1[j].y, d1[j].z, d1[j].w};
#pragma unroll
                for (int cc = 0; cc < 4; ++cc) {
                    const int c = j * 4 + cc;
                    const ulonglong2 w01 = wp[c * 2];         // heads 0-3
                    const ulonglong2 w45 = wp[c * 2 + 1];     // heads 4-7
                    const unsigned long long a0 = pack2(a0v[cc], a0v[cc]);
                    const unsigned long long a1 = pack2(a1v[cc], a1v[cc]);
                    FMA2(acc0[0], a0, w01.x);
                    FMA2(acc0[1], a0, w01.y);
                    FMA2(acc0[2], a0, w45.x);
                    FMA2(acc0[3], a0, w45.y);
                    FMA2(acc1[0], a1, w01.x);
                    FMA2(acc1[1], a1, w01.y);
                    FMA2(acc1[2], a1, w45.x);
                    FMA2(acc1[3], a1, w45.y);
                }
            }
        }

        // ---- epilogue for row bm: exp * roi, reduce, normalize, store ----
        float e0[H], e1[H], sums[H];
        {
            float a0[H], a1[H];
#pragma unroll
            for (int j = 0; j < 4; ++j) {
                unpack2(acc0[j], a0[2 * j], a0[2 * j + 1]);
                unpack2(acc1[j], a1[2 * j], a1[2 * j + 1]);
            }
            const float r0v = roi[(size_t)bm * N + tid];
            const float r1v = roi[(size_t)bm * N + tid + 256];
#pragma unroll
            for (int h = 0; h < H; ++h) {
                e0[h] = __expf(a0[h]) * r0v;
                e1[h] = __expf(a1[h]) * r1v;
                sums[h] = e0[h] + e1[h];
            }
        }

#pragma unroll
        for (int h = 0; h < H; ++h) {
            float s = sums[h];
#pragma unroll
            for (int off = 16; off > 0; off >>= 1)
                s += __shfl_xor_sync(0xffffffffu, s, off);
            sums[h] = s;
        }
        if (lane == 0) {
#pragma unroll
            for (int h = 0; h < H; ++h) wsum[warp * H + h] = sums[h];
        }
        __syncthreads();

        float inv[H];
#pragma unroll
        for (int h = 0; h < H; ++h) {
            float t = 0.f;
#pragma unroll
            for (int w = 0; w < 8; ++w) t += wsum[w * H + h];
            inv[h] = 1.0f / t;
        }
        __syncthreads();   // wsum consumed before next row overwrites

        {
            float* op = out + ((size_t)bm * N + tid) * H;
            float4 a, b2;
            a.x  = e0[0] * inv[0];  a.y  = e0[1] * inv[1];
            a.z  = e0[2] * inv[2];  a.w  = e0[3] * inv[3];
            b2.x = e0[4] * inv[4];  b2.y = e0[5] * inv[5];
            b2.z = e0[6] * inv[6];  b2.w = e0[7] * inv[7];
            *reinterpret_cast<float4*>(op)     = a;
            *reinterpret_cast<float4*>(op + 4) = b2;
        }
        {
            float* op = out + ((size_t)bm * N + tid + 256) * H;
            float4 a, b2;
            a.x  = e1[0] * inv[0];  a.y  = e1[1] * inv[1];
            a.z  = e1[2] * inv[2];  a.w  = e1[3] * inv[3];
            b2.x = e1[4] * inv[4];  b2.y = e1[5] * inv[5];
            b2.z = e1[6] * inv[6];  b2.w = e1[7] * inv[7];
            *reinterpret_cast<float4*>(op)     = a;
            *reinterpret_cast<float4*>(op + 4) = b2;
        }
    }
}

// runtime-resolved driver API (harness doesn't link -lcuda)
typedef CUresult (*EncodeTiledFn)(
    CUtensorMap*, CUtensorMapDataType, cuuint32_t, void*,
    const cuuint64_t*, const cuuint64_t*, const cuuint32_t*, const cuuint32_t*,
    CUtensorMapInterleave, CUtensorMapSwizzle, CUtensorMapL2promotion,
    CUtensorMapFloatOOBfill);

static EncodeTiledFn get_encode_fn() {
    void* fn = nullptr;
    cudaDriverEntryPointQueryResult qr;
    cudaGetDriverEntryPoint("cuTensorMapEncodeTiled", &fn, cudaEnableDefault, &qr);
    return (EncodeTiledFn)fn;
}

static CUtensorMap make_map(EncodeTiledFn enc, const void* ptr) {
    CUtensorMap m{};
    cuuint64_t dims[2]    = {(cuuint64_t)C, (cuuint64_t)B * N * N};
    cuuint64_t strides[1] = {(cuuint64_t)(C * sizeof(float))};
    cuuint32_t box[2]     = {SCH, 256};
    cuuint32_t estr[2]    = {1, 1};
    enc(&m, CU_TENSOR_MAP_DATA_TYPE_FLOAT32, 2,
        const_cast<void*>(ptr), dims, strides, box, estr,
        CU_TENSOR_MAP_INTERLEAVE_NONE,
        CU_TENSOR_MAP_SWIZZLE_64B,
        CU_TENSOR_MAP_L2_PROMOTION_L2_128B,
        CU_TENSOR_MAP_FLOAT_OOB_FILL_NONE);
    return m;
}

} // namespace

extern "C" void kernel_launch(void* const* d_in, const int* in_sizes, int n_in,
                              void* d_out, int out_size)
{
    const float* q    = (const float*)d_in[0];
    const float* k    = (const float*)d_in[1];
    const float* roi  = (const float*)d_in[2];
    const float* W    = (const float*)d_in[3];
    const float* bias = (const float*)d_in[4];
    float* out        = (float*)d_out;

    (void)in_sizes; (void)n_in; (void)out_size;

    EncodeTiledFn enc = get_encode_fn();
    const CUtensorMap qmap = make_map(enc, q);
    const CUtensorMap kmap = make_map(enc, k);

    cudaFuncSetAttribute(mha_fused_kernel,
                         cudaFuncAttributeMaxDynamicSharedMemorySize,
                         (int)SMEM_BYTES);

    dim3 grid(GRID);     // 296 CTAs = 148 SMs x 2; balanced 7/6 rows per SM
    dim3 block(THREADS);
    mha_fused_kernel<<<grid, block, SMEM_BYTES>>>(qmap, kmap, roi, W, bias, out);
}